// round 12
// baseline (speedup 1.0000x reference)
#include <cuda_runtime.h>
#include <cuda_bf16.h>
#include <cstdint>

// ---------------------------------------------------------------------------
// QuantizedLinear — bf16 HMMA GEMM (native mma.sync path on sm_103).
// Walls measured this session: s8 mma.sync = dp4a emulation (~256 MAC/cyc/SM);
// bf16 HMMA f32-acc sustains ~512-550 MAC/cyc/SM; tcgen05 blocked (compute_103).
// Exact: integer values in bf16/f32, all sums < 2^24 -> bit-exact int32 acc.
//   q_in = clip(rint(x/s_in)+zp_in) ; acc = q_in·W^T + bias ;
//   out  = (float)clip(rint((float)acc/s_out)+zp_out)        [f32 out buffer]
// M=8192, K=4096, N=4096.
// Launch 1: prep (quantize + repack), MLP=4.
// Launch 2: GEMM — R10 tiles, NEW 3-stage single-sync multistage mainloop
//           (1 barrier/iter instead of 2; loads issued after the barrier).
// ---------------------------------------------------------------------------

#define MAX_M 8192
#define MAX_K 4096
#define MAX_N 8192

__device__ __nv_bfloat16 g_qin[(size_t)MAX_M * MAX_K];  // quantized input [M,K]
__device__ __nv_bfloat16 g_w[(size_t)MAX_N * MAX_K];    // repacked weight [N,K]
__device__ int           g_bias[MAX_N];

// ---------------- helpers ---------------------------------------------------
__device__ __forceinline__ uint32_t smem_u32(const void* p) {
    uint32_t a;
    asm("{ .reg .u64 t; cvta.to.shared.u64 t, %1; cvt.u32.u64 %0, t; }"
        : "=r"(a) : "l"(p));
    return a;
}
__device__ __forceinline__ float read_scale_f(const void* p, float lo, float hi) {
    float f = *(const float*)p;
    if (isfinite(f) && f > lo && f < hi) return f;
    return (float)(*(const double*)p);
}
__device__ __forceinline__ int clamp_i8(int v) { return max(-128, min(127, v)); }

__device__ __forceinline__ void cp_async16(uint32_t dst, const void* src) {
    asm volatile("cp.async.cg.shared.global [%0], [%1], 16;"
                 :: "r"(dst), "l"(src) : "memory");
}
#define CP_COMMIT() asm volatile("cp.async.commit_group;" ::: "memory")

__device__ __forceinline__ void mma_bf16(float* d, const int* a, const int* b) {
    asm volatile(
        "mma.sync.aligned.m16n8k16.row.col.f32.bf16.bf16.f32 "
        "{%0,%1,%2,%3}, {%4,%5,%6,%7}, {%8,%9}, {%0,%1,%2,%3};"
        : "+f"(d[0]), "+f"(d[1]), "+f"(d[2]), "+f"(d[3])
        : "r"(a[0]), "r"(a[1]), "r"(a[2]), "r"(a[3]),
          "r"(b[0]), "r"(b[1]));
}
__device__ __forceinline__ void ldm_x4(uint32_t addr, int& r0, int& r1,
                                       int& r2, int& r3) {
    asm volatile("ldmatrix.sync.aligned.m8n8.x4.shared.b16 {%0,%1,%2,%3}, [%4];"
                 : "=r"(r0), "=r"(r1), "=r"(r2), "=r"(r3) : "r"(addr));
}

// ---------------- launch 1: prep (MLP=4 batched) -----------------------------
#define PREP_TPB 256
#define PREP_VEC 4

__global__ void prep_kernel(const float4* __restrict__ x,
                            const void* __restrict__ s_p,
                            const int* __restrict__ zp_p,
                            const void* __restrict__ w,
                            const void* __restrict__ b,
                            int n4, int wn4, int n) {
    const int64_t base = (int64_t)blockIdx.x * (PREP_TPB * PREP_VEC) + threadIdx.x;

    if (base < n4) {
        float s = read_scale_f(s_p, 1e-6f, 1e3f);
        int zp = __ldg(zp_p);
        float4 v[PREP_VEC];
        int64_t idx[PREP_VEC];
        bool ok[PREP_VEC];
#pragma unroll
        for (int j = 0; j < PREP_VEC; j++) {
            idx[j] = base + (int64_t)j * PREP_TPB;
            ok[j] = idx[j] < n4;
            if (ok[j]) v[j] = x[idx[j]];
        }
#pragma unroll
        for (int j = 0; j < PREP_VEC; j++) {
            if (!ok[j]) continue;
            __nv_bfloat16 q[4];
            q[0] = __float2bfloat16_rn((float)clamp_i8((int)rintf(v[j].x / s) + zp));
            q[1] = __float2bfloat16_rn((float)clamp_i8((int)rintf(v[j].y / s) + zp));
            q[2] = __float2bfloat16_rn((float)clamp_i8((int)rintf(v[j].z / s) + zp));
            q[3] = __float2bfloat16_rn((float)clamp_i8((int)rintf(v[j].w / s) + zp));
            ((uint2*)g_qin)[idx[j]] = *(const uint2*)q;
        }
        return;
    }

    int64_t jb = base - n4;
    if (jb < wn4) {
        const int* wi = (const int*)w; const float* wf = (const float*)w;
        bool i32 = true, f32 = true;
#pragma unroll
        for (int k = 0; k < 16; k++) {
            int vv = __ldg(&wi[k]);
            if (vv < -128 || vv > 127) i32 = false;
            float f = __ldg(&wf[k]);
            if (!isfinite(f) || f != rintf(f) || fabsf(f) > 128.0f) f32 = false;
        }
        int64_t idx[PREP_VEC];
        bool ok[PREP_VEC];
        float v0[PREP_VEC], v1[PREP_VEC], v2[PREP_VEC], v3[PREP_VEC];
        if (i32) {
            int4 raw[PREP_VEC];
#pragma unroll
            for (int j = 0; j < PREP_VEC; j++) {
                idx[j] = jb + (int64_t)j * PREP_TPB;
                ok[j] = idx[j] < wn4;
                if (ok[j]) raw[j] = ((const int4*)w)[idx[j]];
            }
#pragma unroll
            for (int j = 0; j < PREP_VEC; j++) {
                v0[j] = (float)raw[j].x; v1[j] = (float)raw[j].y;
                v2[j] = (float)raw[j].z; v3[j] = (float)raw[j].w;
            }
        } else if (f32) {
            float4 raw[PREP_VEC];
#pragma unroll
            for (int j = 0; j < PREP_VEC; j++) {
                idx[j] = jb + (int64_t)j * PREP_TPB;
                ok[j] = idx[j] < wn4;
                if (ok[j]) raw[j] = ((const float4*)w)[idx[j]];
            }
#pragma unroll
            for (int j = 0; j < PREP_VEC; j++) {
                v0[j] = rintf(raw[j].x); v1[j] = rintf(raw[j].y);
                v2[j] = rintf(raw[j].z); v3[j] = rintf(raw[j].w);
            }
        } else {
            char4 raw[PREP_VEC];
#pragma unroll
            for (int j = 0; j < PREP_VEC; j++) {
                idx[j] = jb + (int64_t)j * PREP_TPB;
                ok[j] = idx[j] < wn4;
                if (ok[j]) raw[j] = ((const char4*)w)[idx[j]];
            }
#pragma unroll
            for (int j = 0; j < PREP_VEC; j++) {
                v0[j] = (float)raw[j].x; v1[j] = (float)raw[j].y;
                v2[j] = (float)raw[j].z; v3[j] = (float)raw[j].w;
            }
        }
#pragma unroll
        for (int j = 0; j < PREP_VEC; j++) {
            if (!ok[j]) continue;
            __nv_bfloat16 q[4];
            q[0] = __float2bfloat16_rn(v0[j]); q[1] = __float2bfloat16_rn(v1[j]);
            q[2] = __float2bfloat16_rn(v2[j]); q[3] = __float2bfloat16_rn(v3[j]);
            ((uint2*)g_w)[idx[j]] = *(const uint2*)q;
        }
        return;
    }

    int64_t kb = jb - wn4;
    const int* bi = (const int*)b; const float* bf = (const float*)b;
    bool i32 = true;
#pragma unroll
    for (int q = 0; q < 16; q++)
        if (__ldg(&bi[q]) < -32768 || __ldg(&bi[q]) > 32767) i32 = false;
#pragma unroll
    for (int j = 0; j < PREP_VEC; j++) {
        int64_t k = kb + (int64_t)j * PREP_TPB;
        if (k < n)
            g_bias[k] = i32 ? ((const int*)b)[k] : (int)rintf(((const float*)b)[k]);
    }
}

// ---------------- launch 2: bf16 HMMA GEMM, 3-stage single-sync -------------
#define BM 128
#define BN 128
#define BKE 64           // K elements per stage (= 128 bytes per row)
#define PAD_ROW 144      // 128 data bytes + 16 pad -> ldmatrix conflict-free
#define STAGE_BYTES ((BM + BN) * PAD_ROW)   // 36864
#define NSTAGE 3         // 3 x 36864 = 110592 B/CTA ; x2 CTAs = 221184 <= 228KB

extern __shared__ int8_t dsmem[];

__global__ __launch_bounds__(256, 2)
void gemm_bf16_kernel(float* __restrict__ C, int M, int N, int K,
                      const void* __restrict__ os_p,
                      const int* __restrict__ ozp_p) {
    const int t   = threadIdx.x;
    const int wid = t >> 5;
    const int lid = t & 31;
    const int g   = lid >> 2;
    const int t4  = lid & 3;
    const int wm  = wid >> 2;      // 0..1
    const int wn  = wid & 3;       // 0..3
    const int bm  = blockIdx.y * BM;
    const int bn  = blockIdx.x * BN;

    const uint32_t sA0 = smem_u32(dsmem);
    const uint32_t sB0 = sA0 + BM * PAD_ROW;

    const size_t Kb = (size_t)K * 2;
    const char* gA = (const char*)g_qin + (size_t)bm * Kb;
    const char* gB = (const char*)g_w   + (size_t)bn * Kb;

    float acc[4][4][4];
#pragma unroll
    for (int i = 0; i < 4; i++)
#pragma unroll
        for (int j = 0; j < 4; j++)
#pragma unroll
            for (int r = 0; r < 4; r++) acc[i][j][r] = 0.0f;

    auto load_tiles = [&](int stage, int kbyte0) {
        uint32_t so = stage * STAGE_BYTES;
#pragma unroll
        for (int l = 0; l < 4; l++) {
            int c   = t + l * 256;
            int row = c >> 3;
            int seg = (c & 7) * 16;
            uint32_t doff = so + row * PAD_ROW + seg;
            const size_t goff = (size_t)row * Kb + kbyte0 + seg;
            cp_async16(sA0 + doff, gA + goff);
            cp_async16(sB0 + doff, gB + goff);
        }
        CP_COMMIT();
    };

    const int lm_row = (lid & 7) + ((lid >> 3) & 1) * 8;
    const int lm_col = (lid >> 4) * 16;
    uint32_t a_base[4], b_base[2];
#pragma unroll
    for (int mt = 0; mt < 4; mt++)
        a_base[mt] = sA0 + (wm * 64 + mt * 16 + lm_row) * PAD_ROW + lm_col;
#pragma unroll
    for (int p = 0; p < 2; p++)
        b_base[p] = sB0 + (wn * 32 + p * 16 + lm_row) * PAD_ROW + lm_col;

    const int niter = K / BKE;          // 64

    // prologue: 2 stages in flight
    load_tiles(0, 0);
    load_tiles(1, BKE * 2);

    // Multistage loop, ONE barrier per iteration:
    //   wait_group(1)  -> stage it%3 complete (for this thread)
    //   __syncthreads  -> complete for ALL threads; also: every warp has
    //                     finished reading stage (it-1)%3 == (it+2)%3, so the
    //                     load issued below cannot clobber in-flight reads.
    //   load_tiles     -> overlaps with compute below
    for (int it = 0; it < niter; it++) {
        asm volatile("cp.async.wait_group 1;" ::: "memory");
        __syncthreads();
        if (it + 2 < niter)
            load_tiles((it + 2) % NSTAGE, (it + 2) * (BKE * 2));

        const uint32_t so = (uint32_t)(it % NSTAGE) * STAGE_BYTES;
#pragma unroll
        for (int ks = 0; ks < 4; ks++) {
            const uint32_t kb = so + ks * 32;
            int af[4][4], bf[4][2];
#pragma unroll
            for (int mt = 0; mt < 4; mt++)
                ldm_x4(a_base[mt] + kb, af[mt][0], af[mt][1], af[mt][2], af[mt][3]);
#pragma unroll
            for (int p = 0; p < 2; p++) {
                int r0, r1, r2, r3;
                ldm_x4(b_base[p] + kb, r0, r1, r2, r3);
                bf[2 * p][0]     = r0;
                bf[2 * p + 1][0] = r1;
                bf[2 * p][1]     = r2;
                bf[2 * p + 1][1] = r3;
            }
#pragma unroll
            for (int mt = 0; mt < 4; mt++)
#pragma unroll
                for (int nt = 0; nt < 4; nt++)
                    mma_bf16(acc[mt][nt], af[mt], bf[nt]);
        }
    }

    // ---------------- epilogue ----------------------------------------------
    const float os = read_scale_f(os_p, 1e-3f, 1e9f);
    const int ozp = __ldg(ozp_p);

#pragma unroll
    for (int mt = 0; mt < 4; mt++) {
        const int row0 = bm + wm * 64 + mt * 16 + g;
#pragma unroll
        for (int nt = 0; nt < 4; nt++) {
            const int col0 = bn + wn * 32 + nt * 8 + t4 * 2;
            const float b0 = (float)g_bias[col0];
            const float b1 = (float)g_bias[col0 + 1];
            float2 lo, hi;
            lo.x = (float)clamp_i8((int)rintf((acc[mt][nt][0] + b0) / os) + ozp);
            lo.y = (float)clamp_i8((int)rintf((acc[mt][nt][1] + b1) / os) + ozp);
            hi.x = (float)clamp_i8((int)rintf((acc[mt][nt][2] + b0) / os) + ozp);
            hi.y = (float)clamp_i8((int)rintf((acc[mt][nt][3] + b1) / os) + ozp);
            *(float2*)&C[(size_t)row0 * N + col0]       = lo;
            *(float2*)&C[(size_t)(row0 + 8) * N + col0] = hi;
        }
    }
}

// ---------------------------------------------------------------------------
extern "C" void kernel_launch(void* const* d_in, const int* in_sizes, int n_in,
                              void* d_out, int out_size) {
    const float* input  = (const float*)d_in[0];
    const void*  weight = d_in[1];
    const void*  bias   = d_in[2];
    const void*  in_s   = d_in[3];
    const int*   in_zp  = (const int*)d_in[4];
    const void*  out_s  = d_in[5];
    const int*   out_zp = (const int*)d_in[6];

    const int N = in_sizes[2];
    const int K = in_sizes[1] / N;
    const int M = in_sizes[0] / K;

    float* out = (float*)d_out;

    long long n4  = (long long)(M) * K / 4;
    long long wn4 = (long long)(N) * K / 4;
    long long per_blk = PREP_TPB * PREP_VEC;
    long long tot = n4 + wn4 + N;
    int blocks = (int)((tot + per_blk - 1) / per_blk) + 2;
    prep_kernel<<<blocks, PREP_TPB>>>((const float4*)input, in_s, in_zp,
                                      weight, bias, (int)n4, (int)wn4, N);

    cudaFuncSetAttribute(gemm_bf16_kernel,
                         cudaFuncAttributeMaxDynamicSharedMemorySize,
                         NSTAGE * STAGE_BYTES);
    dim3 grid(N / BN, M / BM);
    gemm_bf16_kernel<<<grid, 256, NSTAGE * STAGE_BYTES>>>(out, M, N, K,
                                                          out_s, out_zp);
}

// round 13
// speedup vs baseline: 1.0165x; 1.0165x over previous
#include <cuda_runtime.h>
#include <cuda_bf16.h>
#include <cstdint>

// ---------------------------------------------------------------------------
// QuantizedLinear — bf16 HMMA GEMM (native mma.sync path on sm_103).
// Session findings (measured):
//   * s8 mma.sync  = dp4a-pipe emulation (~256 MAC/cyc/SM)  -> unusable
//   * bf16 HMMA f32-acc issue rate = ~512 MAC/cyc/SM; 5 schedule variants all
//     converge there -> GEMM below is AT the hardware wall (842.9us)
//   * tcgen05 blocked: harness compiles PTX at compute_103 ('a'-gated ISA)
//   * prep at HBM traffic floor (~36us for 288MB)
// Exact: integer values in bf16/f32, all sums < 2^24 -> bit-exact int32 acc.
//   q_in = clip(rint(x/s_in)+zp_in) ; acc = q_in·W^T + bias ;
//   out  = (float)clip(rint((float)acc/s_out)+zp_out)        [f32 out buffer]
// M=8192, K=4096, N=4096.
// Launch 1: prep (quantize + repack), MLP=4, 16B stores.
// Launch 2: GEMM — R11 config verbatim (CTA 128x128, 8 warps @ 64x32,
//           2-stage cp.async, ldmatrix.x4, 2 CTAs/SM).
// ---------------------------------------------------------------------------

#define MAX_M 8192
#define MAX_K 4096
#define MAX_N 8192

__device__ __nv_bfloat16 g_qin[(size_t)MAX_M * MAX_K];  // quantized input [M,K]
__device__ __nv_bfloat16 g_w[(size_t)MAX_N * MAX_K];    // repacked weight [N,K]
__device__ int           g_bias[MAX_N];

// ---------------- helpers ---------------------------------------------------
__device__ __forceinline__ uint32_t smem_u32(const void* p) {
    uint32_t a;
    asm("{ .reg .u64 t; cvta.to.shared.u64 t, %1; cvt.u32.u64 %0, t; }"
        : "=r"(a) : "l"(p));
    return a;
}
__device__ __forceinline__ float read_scale_f(const void* p, float lo, float hi) {
    float f = *(const float*)p;
    if (isfinite(f) && f > lo && f < hi) return f;
    return (float)(*(const double*)p);
}
__device__ __forceinline__ int clamp_i8(int v) { return max(-128, min(127, v)); }

__device__ __forceinline__ void cp_async16(uint32_t dst, const void* src) {
    asm volatile("cp.async.cg.shared.global [%0], [%1], 16;"
                 :: "r"(dst), "l"(src) : "memory");
}
#define CP_COMMIT() asm volatile("cp.async.commit_group;" ::: "memory")

__device__ __forceinline__ void mma_bf16(float* d, const int* a, const int* b) {
    asm volatile(
        "mma.sync.aligned.m16n8k16.row.col.f32.bf16.bf16.f32 "
        "{%0,%1,%2,%3}, {%4,%5,%6,%7}, {%8,%9}, {%0,%1,%2,%3};"
        : "+f"(d[0]), "+f"(d[1]), "+f"(d[2]), "+f"(d[3])
        : "r"(a[0]), "r"(a[1]), "r"(a[2]), "r"(a[3]),
          "r"(b[0]), "r"(b[1]));
}
__device__ __forceinline__ void ldm_x4(uint32_t addr, int& r0, int& r1,
                                       int& r2, int& r3) {
    asm volatile("ldmatrix.sync.aligned.m8n8.x4.shared.b16 {%0,%1,%2,%3}, [%4];"
                 : "=r"(r0), "=r"(r1), "=r"(r2), "=r"(r3) : "r"(addr));
}

// bf16x8 pack: two float4 -> one uint4 (16B store)
__device__ __forceinline__ uint4 pack_bf16x8(float a0, float a1, float a2, float a3,
                                             float b0, float b1, float b2, float b3) {
    __nv_bfloat16 q[8] = {
        __float2bfloat16_rn(a0), __float2bfloat16_rn(a1),
        __float2bfloat16_rn(a2), __float2bfloat16_rn(a3),
        __float2bfloat16_rn(b0), __float2bfloat16_rn(b1),
        __float2bfloat16_rn(b2), __float2bfloat16_rn(b3)};
    return *(const uint4*)q;
}

// ---------------- launch 1: prep -------------------------------------------
// Work unit = 8 source elements (two float4 chunks) -> one 16B bf16 store.
// Each thread processes PREP_BAT units with independent loads (MLP=4).
#define PREP_TPB 256
#define PREP_BAT 2

__global__ void prep_kernel(const float4* __restrict__ x,
                            const void* __restrict__ s_p,
                            const int* __restrict__ zp_p,
                            const void* __restrict__ w,
                            const void* __restrict__ b,
                            int n8, int wn8, int n) {
    const int64_t base = (int64_t)blockIdx.x * (PREP_TPB * PREP_BAT) + threadIdx.x;

    if (base < n8) {
        // ---- input quantization: 2x float4 -> 8x bf16 (one uint4 store) ----
        float s = read_scale_f(s_p, 1e-6f, 1e3f);
        int zp = __ldg(zp_p);
        float4 v[PREP_BAT][2];
        int64_t idx[PREP_BAT];
        bool ok[PREP_BAT];
#pragma unroll
        for (int j = 0; j < PREP_BAT; j++) {
            idx[j] = base + (int64_t)j * PREP_TPB;
            ok[j] = idx[j] < n8;
            if (ok[j]) {
                v[j][0] = x[idx[j] * 2];      // 4 independent LDG.128 total
                v[j][1] = x[idx[j] * 2 + 1];
            }
        }
#pragma unroll
        for (int j = 0; j < PREP_BAT; j++) {
            if (!ok[j]) continue;
            ((uint4*)g_qin)[idx[j]] = pack_bf16x8(
                (float)clamp_i8((int)rintf(v[j][0].x / s) + zp),
                (float)clamp_i8((int)rintf(v[j][0].y / s) + zp),
                (float)clamp_i8((int)rintf(v[j][0].z / s) + zp),
                (float)clamp_i8((int)rintf(v[j][0].w / s) + zp),
                (float)clamp_i8((int)rintf(v[j][1].x / s) + zp),
                (float)clamp_i8((int)rintf(v[j][1].y / s) + zp),
                (float)clamp_i8((int)rintf(v[j][1].z / s) + zp),
                (float)clamp_i8((int)rintf(v[j][1].w / s) + zp));
        }
        return;
    }

    int64_t jb = base - n8;
    if (jb < wn8) {
        // ---- weight repack (dtype-detected): 8 elems -> one uint4 store ----
        const int* wi = (const int*)w; const float* wf = (const float*)w;
        bool i32 = true, f32 = true;
#pragma unroll
        for (int k = 0; k < 16; k++) {
            int vv = __ldg(&wi[k]);
            if (vv < -128 || vv > 127) i32 = false;
            float f = __ldg(&wf[k]);
            if (!isfinite(f) || f != rintf(f) || fabsf(f) > 128.0f) f32 = false;
        }
        int64_t idx[PREP_BAT];
        bool ok[PREP_BAT];
        float e[PREP_BAT][8];
        if (i32) {
            int4 raw[PREP_BAT][2];
#pragma unroll
            for (int j = 0; j < PREP_BAT; j++) {
                idx[j] = jb + (int64_t)j * PREP_TPB;
                ok[j] = idx[j] < wn8;
                if (ok[j]) {
                    raw[j][0] = ((const int4*)w)[idx[j] * 2];
                    raw[j][1] = ((const int4*)w)[idx[j] * 2 + 1];
                }
            }
#pragma unroll
            for (int j = 0; j < PREP_BAT; j++) {
                e[j][0] = (float)raw[j][0].x; e[j][1] = (float)raw[j][0].y;
                e[j][2] = (float)raw[j][0].z; e[j][3] = (float)raw[j][0].w;
                e[j][4] = (float)raw[j][1].x; e[j][5] = (float)raw[j][1].y;
                e[j][6] = (float)raw[j][1].z; e[j][7] = (float)raw[j][1].w;
            }
        } else if (f32) {
            float4 raw[PREP_BAT][2];
#pragma unroll
            for (int j = 0; j < PREP_BAT; j++) {
                idx[j] = jb + (int64_t)j * PREP_TPB;
                ok[j] = idx[j] < wn8;
                if (ok[j]) {
                    raw[j][0] = ((const float4*)w)[idx[j] * 2];
                    raw[j][1] = ((const float4*)w)[idx[j] * 2 + 1];
                }
            }
#pragma unroll
            for (int j = 0; j < PREP_BAT; j++) {
                e[j][0] = rintf(raw[j][0].x); e[j][1] = rintf(raw[j][0].y);
                e[j][2] = rintf(raw[j][0].z); e[j][3] = rintf(raw[j][0].w);
                e[j][4] = rintf(raw[j][1].x); e[j][5] = rintf(raw[j][1].y);
                e[j][6] = rintf(raw[j][1].z); e[j][7] = rintf(raw[j][1].w);
            }
        } else {
            char4 raw[PREP_BAT][2];
#pragma unroll
            for (int j = 0; j < PREP_BAT; j++) {
                idx[j] = jb + (int64_t)j * PREP_TPB;
                ok[j] = idx[j] < wn8;
                if (ok[j]) {
                    raw[j][0] = ((const char4*)w)[idx[j] * 2];
                    raw[j][1] = ((const char4*)w)[idx[j] * 2 + 1];
                }
            }
#pragma unroll
            for (int j = 0; j < PREP_BAT; j++) {
                e[j][0] = (float)raw[j][0].x; e[j][1] = (float)raw[j][0].y;
                e[j][2] = (float)raw[j][0].z; e[j][3] = (float)raw[j][0].w;
                e[j][4] = (float)raw[j][1].x; e[j][5] = (float)raw[j][1].y;
                e[j][6] = (float)raw[j][1].z; e[j][7] = (float)raw[j][1].w;
            }
        }
#pragma unroll
        for (int j = 0; j < PREP_BAT; j++) {
            if (!ok[j]) continue;
            ((uint4*)g_w)[idx[j]] = pack_bf16x8(e[j][0], e[j][1], e[j][2], e[j][3],
                                                e[j][4], e[j][5], e[j][6], e[j][7]);
        }
        return;
    }

    // ---- bias ----
    int64_t kb = jb - wn8;
    const int* bi = (const int*)b; const float* bf = (const float*)b;
    bool i32 = true;
#pragma unroll
    for (int q = 0; q < 16; q++)
        if (__ldg(&bi[q]) < -32768 || __ldg(&bi[q]) > 32767) i32 = false;
#pragma unroll
    for (int j = 0; j < PREP_BAT; j++) {
        int64_t k = kb + (int64_t)j * PREP_TPB;
        if (k < n)
            g_bias[k] = i32 ? ((const int*)b)[k] : (int)rintf(((const float*)b)[k]);
    }
}

// ---------------- launch 2: bf16 HMMA GEMM (R11 config, verbatim) -----------
#define BM 128
#define BN 128
#define BKE 64           // K elements per stage (= 128 bytes per row)
#define PAD_ROW 144      // 128 data bytes + 16 pad -> ldmatrix conflict-free
#define STAGE_BYTES ((BM + BN) * PAD_ROW)

extern __shared__ int8_t dsmem[];

__global__ __launch_bounds__(256, 2)
void gemm_bf16_kernel(float* __restrict__ C, int M, int N, int K,
                      const void* __restrict__ os_p,
                      const int* __restrict__ ozp_p) {
    const int t   = threadIdx.x;
    const int wid = t >> 5;
    const int lid = t & 31;
    const int g   = lid >> 2;      // groupID 0..7
    const int t4  = lid & 3;
    const int wm  = wid >> 2;      // 0..1
    const int wn  = wid & 3;       // 0..3
    const int bm  = blockIdx.y * BM;
    const int bn  = blockIdx.x * BN;

    const uint32_t sA0 = smem_u32(dsmem);
    const uint32_t sB0 = sA0 + BM * PAD_ROW;

    const size_t Kb = (size_t)K * 2;   // row stride in bytes
    const char* gA = (const char*)g_qin + (size_t)bm * Kb;
    const char* gB = (const char*)g_w   + (size_t)bn * Kb;

    float acc[4][4][4];
#pragma unroll
    for (int i = 0; i < 4; i++)
#pragma unroll
        for (int j = 0; j < 4; j++)
#pragma unroll
            for (int r = 0; r < 4; r++) acc[i][j][r] = 0.0f;

    // tile loader: 128 rows x 128B per side -> 1024 chunks, 4/thread/side
    auto load_tiles = [&](int stage, int kbyte0) {
        uint32_t so = stage * STAGE_BYTES;
#pragma unroll
        for (int l = 0; l < 4; l++) {
            int c   = t + l * 256;     // 0..1023
            int row = c >> 3;          // 0..127
            int seg = (c & 7) * 16;    // 0..112 bytes
            uint32_t doff = so + row * PAD_ROW + seg;
            const size_t goff = (size_t)row * Kb + kbyte0 + seg;
            cp_async16(sA0 + doff, gA + goff);
            cp_async16(sB0 + doff, gB + goff);
        }
        CP_COMMIT();
    };

    // ldmatrix addressing: row = (lid&7)+((lid>>3)&1)*8 ; byte col = (lid>>4)*16
    const int lm_row = (lid & 7) + ((lid >> 3) & 1) * 8;
    const int lm_col = (lid >> 4) * 16;
    uint32_t a_base[4], b_base[2];
#pragma unroll
    for (int mt = 0; mt < 4; mt++)
        a_base[mt] = sA0 + (wm * 64 + mt * 16 + lm_row) * PAD_ROW + lm_col;
#pragma unroll
    for (int p = 0; p < 2; p++)
        b_base[p] = sB0 + (wn * 32 + p * 16 + lm_row) * PAD_ROW + lm_col;

    const int niter = K / BKE;          // 64
    load_tiles(0, 0);

    for (int it = 0; it < niter; it++) {
        if (it + 1 < niter) {
            load_tiles((it + 1) & 1, (it + 1) * (BKE * 2));
            asm volatile("cp.async.wait_group 1;" ::: "memory");
        } else {
            asm volatile("cp.async.wait_group 0;" ::: "memory");
        }
        __syncthreads();

        const uint32_t so = (uint32_t)(it & 1) * STAGE_BYTES;
#pragma unroll
        for (int ks = 0; ks < 4; ks++) {          // 4 x k16 steps (32B each)
            const uint32_t kb = so + ks * 32;
            int af[4][4], bf[4][2];
#pragma unroll
            for (int mt = 0; mt < 4; mt++)
                ldm_x4(a_base[mt] + kb, af[mt][0], af[mt][1], af[mt][2], af[mt][3]);
#pragma unroll
            for (int p = 0; p < 2; p++) {
                int r0, r1, r2, r3;
                ldm_x4(b_base[p] + kb, r0, r1, r2, r3);
                bf[2 * p][0]     = r0;  // n 0-7,  k0-7
                bf[2 * p + 1][0] = r1;  // n 8-15, k0-7
                bf[2 * p][1]     = r2;  // n 0-7,  k8-15
                bf[2 * p + 1][1] = r3;  // n 8-15, k8-15
            }
#pragma unroll
            for (int mt = 0; mt < 4; mt++)
#pragma unroll
                for (int nt = 0; nt < 4; nt++)
                    mma_bf16(acc[mt][nt], af[mt], bf[nt]);
        }
        __syncthreads();
    }

    // ---------------- epilogue ----------------------------------------------
    const float os = read_scale_f(os_p, 1e-3f, 1e9f);
    const int ozp = __ldg(ozp_p);

#pragma unroll
    for (int mt = 0; mt < 4; mt++) {
        const int row0 = bm + wm * 64 + mt * 16 + g;
#pragma unroll
        for (int nt = 0; nt < 4; nt++) {
            const int col0 = bn + wn * 32 + nt * 8 + t4 * 2;
            const float b0 = (float)g_bias[col0];
            const float b1 = (float)g_bias[col0 + 1];
            float2 lo, hi;
            lo.x = (float)clamp_i8((int)rintf((acc[mt][nt][0] + b0) / os) + ozp);
            lo.y = (float)clamp_i8((int)rintf((acc[mt][nt][1] + b1) / os) + ozp);
            hi.x = (float)clamp_i8((int)rintf((acc[mt][nt][2] + b0) / os) + ozp);
            hi.y = (float)clamp_i8((int)rintf((acc[mt][nt][3] + b1) / os) + ozp);
            *(float2*)&C[(size_t)row0 * N + col0]       = lo;
            *(float2*)&C[(size_t)(row0 + 8) * N + col0] = hi;
        }
    }
}

// ---------------------------------------------------------------------------
extern "C" void kernel_launch(void* const* d_in, const int* in_sizes, int n_in,
                              void* d_out, int out_size) {
    const float* input  = (const float*)d_in[0];
    const void*  weight = d_in[1];
    const void*  bias   = d_in[2];
    const void*  in_s   = d_in[3];
    const int*   in_zp  = (const int*)d_in[4];
    const void*  out_s  = d_in[5];
    const int*   out_zp = (const int*)d_in[6];

    const int N = in_sizes[2];
    const int K = in_sizes[1] / N;
    const int M = in_sizes[0] / K;

    float* out = (float*)d_out;

    // prep: work units of 8 elements
    long long n8  = (long long)M * K / 8;
    long long wn8 = (long long)N * K / 8;
    long long per_blk = PREP_TPB * PREP_BAT;
    long long tot = n8 + wn8 + N;
    int blocks = (int)((tot + per_blk - 1) / per_blk) + 2;
    prep_kernel<<<blocks, PREP_TPB>>>((const float4*)input, in_s, in_zp,
                                      weight, bias, (int)n8, (int)wn8, N);

    cudaFuncSetAttribute(gemm_bf16_kernel,
                         cudaFuncAttributeMaxDynamicSharedMemorySize,
                         2 * STAGE_BYTES);
    dim3 grid(N / BN, M / BM);
    gemm_bf16_kernel<<<grid, 256, 2 * STAGE_BYTES>>>(out, M, N, K, out_s, out_zp);
}